// round 11
// baseline (speedup 1.0000x reference)
#include <cuda_runtime.h>
#include <cuda_fp16.h>

#define TT  30
#define TD  150
#define DIM 512
#define MAX_ROWS 34836       // WORDS_CNT + 1
#define ROWS_PER_CTA 16      // rows converted per convert-CTA
#define F4_PER_CTA   (ROWS_PER_CTA * DIM / 4)   // 2048 float4
#define SC_SHIFT 11          // 2048 rows per super-chunk
#define MAX_SC 32

// fp16 copy of the embedding table + progress counters (zero-init .bss)
__device__ __half g_w2v_h[(size_t)MAX_ROWS * DIM];
__device__ int    g_cnt[MAX_SC];

__device__ __forceinline__ void proc_token(
    const char* hbase, int off,
    __half2& mx0, __half2& mx1, __half2& mx2, __half2& mx3,
    float& s0, float& s1, float& s2, float& s3,
    float& s4, float& s5, float& s6, float& s7)
{
    const uint4 u = *(const uint4*)(hbase + off);
    const __half2 h0 = *(const __half2*)&u.x, h1 = *(const __half2*)&u.y;
    const __half2 h2 = *(const __half2*)&u.z, h3 = *(const __half2*)&u.w;
    mx0 = __hmax2(mx0, h0); mx1 = __hmax2(mx1, h1);
    mx2 = __hmax2(mx2, h2); mx3 = __hmax2(mx3, h3);
    float2 f;
    f = __half22float2(h0); s0 += f.x; s1 += f.y;
    f = __half22float2(h1); s2 += f.x; s3 += f.y;
    f = __half22float2(h2); s4 += f.x; s5 += f.y;
    f = __half22float2(h3); s6 += f.x; s7 += f.y;
}

__global__ __launch_bounds__(32)
void fused_kernel(const float4* __restrict__ w2v4,
                  const void* __restrict__ title_v,
                  const void* __restrict__ desc_v,
                  const void* __restrict__ tlen_v,
                  const void* __restrict__ dlen_v,
                  float* __restrict__ out,
                  int B, int nconv, int nsc, int total4)
{
    const int tid = threadIdx.x;

    // ======================= CONVERT CTAs (blockIdx < nconv) =================
    if ((int)blockIdx.x < nconv) {
        const int cta  = blockIdx.x;
        const int base = cta * F4_PER_CTA;
        uint2* dst = (uint2*)g_w2v_h;
        const int limit = min(F4_PER_CTA, total4 - base);
        #pragma unroll 8
        for (int k = tid; k < limit; k += 32) {
            float4 f = __ldcs(&w2v4[base + k]);
            __half2 a = __floats2half2_rn(f.x, f.y);
            __half2 b = __floats2half2_rn(f.z, f.w);
            uint2 u;
            u.x = *reinterpret_cast<unsigned*>(&a);
            u.y = *reinterpret_cast<unsigned*>(&b);
            dst[base + k] = u;
        }
        __syncthreads();
        __threadfence();
        if (tid == 0) atomicAdd(&g_cnt[cta >> 7], 1);   // 128 CTAs per super-chunk
        return;
    }

    // ======================= GATHER CTAs =====================================
    __shared__ int           s_off[TD];    // byte offsets (idx * 1024)
    __shared__ unsigned char s_sc[TD];     // super-chunk of each token
    __shared__ unsigned char s_done[TD];
    __shared__ short         s_list[TD];
    __shared__ int           s_len;
    __shared__ int           s_is64;

    const int gcta   = blockIdx.x - nconv;
    const bool isDesc = (gcta < 2 * B);
    const int local   = isDesc ? gcta : (gcta - 2 * B);
    const int b       = local >> 1;
    const int half    = local & 1;
    const int nTok    = isDesc ? TD : TT;

    // dtype detection: int64 vs int32 indices (values < 34836 => high word 0)
    {
        unsigned hi  = ((const unsigned*)title_v)[2 * tid + 1];
        unsigned any = __ballot_sync(0xffffffffu, hi != 0u);
        if (tid == 0) s_is64 = (any == 0u) ? 1 : 0;
    }
    __syncthreads();

    const void* idx_v = isDesc ? desc_v : title_v;
    const void* len_v = isDesc ? dlen_v : tlen_v;

    if (s_is64) {
        const long long* ip = (const long long*)idx_v + (long long)b * nTok;
        for (int i = tid; i < nTok; i += 32) {
            int r = (int)ip[i];
            s_off[i] = r << 10;
            s_sc[i]  = (unsigned char)(r >> SC_SHIFT);
            s_done[i] = 0;
        }
        if (tid == 0) s_len = (int)((const long long*)len_v)[b];
    } else {
        const int* ip = (const int*)idx_v + b * nTok;
        for (int i = tid; i < nTok; i += 32) {
            int r = ip[i];
            s_off[i] = r << 10;
            s_sc[i]  = (unsigned char)(r >> SC_SHIFT);
            s_done[i] = 0;
        }
        if (tid == 0) s_len = ((const int*)len_v)[b];
    }
    __syncthreads();

    const int len = s_len;
    const char* hbase = (const char*)g_w2v_h + half * 512 + tid * 16;
    float* orow = out + (size_t)b * (4 * DIM) + (isDesc ? DIM : 0)
                      + half * 256 + tid * 8;

    const __half2 NEGH2 = __halves2half2(__ushort_as_half(0xFC00),
                                         __ushort_as_half(0xFC00));

    __half2 mx0 = NEGH2, mx1 = NEGH2, mx2 = NEGH2, mx3 = NEGH2;
    float s0=0.f, s1=0.f, s2=0.f, s3=0.f, s4=0.f, s5=0.f, s6=0.f, s7=0.f;

    // ---- opportunistic phase: process tokens as their chunk converts --------
    int remaining = len;
    const unsigned fullm = (1u << nsc) - 1u;
    const int mytgt = (tid < nsc) ? min(128, nconv - tid * 128) : 1;
    unsigned curmask = 0;
    int guard = 0;
    while (remaining > 0) {
        int c = 0;
        if (tid < nsc) c = *(volatile int*)&g_cnt[tid];
        unsigned m = __ballot_sync(0xffffffffu, (tid < nsc) && (c >= mytgt));
        __threadfence();                       // acquire: order table reads after flags
        if (m == fullm) break;                 // conversion complete -> bulk path
        if (m != curmask) {
            curmask = m;
            for (int t = 0; t < len; t++) {
                if (!s_done[t] && ((m >> s_sc[t]) & 1u)) {
                    proc_token(hbase, s_off[t], mx0, mx1, mx2, mx3,
                               s0, s1, s2, s3, s4, s5, s6, s7);
                    s_done[t] = 1;
                    remaining--;
                }
            }
        } else {
            __nanosleep(256);
        }
        if (++guard > (1 << 21)) break;        // safety valve (never trips normally)
    }

    // ---- bulk phase: everything left is ready ------------------------------
    if (remaining > 0) {
        int n = 0;
        for (int t = 0; t < len; t++)
            if (!s_done[t]) s_list[n++] = (short)t;   // redundant identical writes
        #pragma unroll 4
        for (int j = 0; j < n; j++) {
            proc_token(hbase, s_off[s_list[j]], mx0, mx1, mx2, mx3,
                       s0, s1, s2, s3, s4, s5, s6, s7);
        }
    }

    // ---- epilogue ------------------------------------------------------------
    float4 mxa, mxb, ava, avb;
    if (len > 0) {
        float2 m0 = __half22float2(mx0), m1 = __half22float2(mx1);
        float2 m2 = __half22float2(mx2), m3 = __half22float2(mx3);
        mxa = make_float4(m0.x, m0.y, m1.x, m1.y);
        mxb = make_float4(m2.x, m2.y, m3.x, m3.y);
        const float inv = 1.0f / (float)len;
        ava = make_float4(s0 * inv, s1 * inv, s2 * inv, s3 * inv);
        avb = make_float4(s4 * inv, s5 * inv, s6 * inv, s7 * inv);
    } else {
        mxa = mxb = ava = avb = make_float4(0.f, 0.f, 0.f, 0.f);
    }
    *(float4*)(orow)               = mxa;   // max quadrant
    *(float4*)(orow + 4)           = mxb;
    *(float4*)(orow + 2 * DIM)     = ava;   // avg quadrant
    *(float4*)(orow + 2 * DIM + 4) = avb;
}

// reset progress counters so the next graph replay starts clean
__global__ void reset_kernel()
{
    if (threadIdx.x < MAX_SC) g_cnt[threadIdx.x] = 0;
}

extern "C" void kernel_launch(void* const* d_in, const int* in_sizes, int n_in,
                              void* d_out, int out_size)
{
    const void* title = d_in[0];
    const void* desc  = d_in[1];
    const void* tlen  = d_in[2];
    const void* dlen  = d_in[3];
    const float* w2v  = (const float*)d_in[n_in - 1];
    float* out        = (float*)d_out;

    const int B = in_sizes[2];                        // t_len has B elements

    long long w2v_elems = in_sizes[n_in - 1];
    long long rows = w2v_elems / DIM;
    if (rows > MAX_ROWS) rows = MAX_ROWS;
    const int total4 = (int)(rows * (DIM / 4));       // float4 chunks
    const int nconv  = (int)((rows + ROWS_PER_CTA - 1) / ROWS_PER_CTA);
    const int nsc    = (nconv + 127) / 128;           // super-chunks (<=32)

    const int grid = nconv + 4 * B;
    fused_kernel<<<grid, 32>>>((const float4*)w2v, title, desc, tlen, dlen,
                               out, B, nconv, nsc, total4);
    reset_kernel<<<1, 32>>>();
}

// round 12
// speedup vs baseline: 2.3563x; 2.3563x over previous
#include <cuda_runtime.h>
#include <cuda_fp16.h>

#define TT  30
#define TD  150
#define DIM 512
#define MAX_ROWS 34836   // WORDS_CNT + 1

// fp16 copy of the embedding table (zero-init .bss, no allocation)
__device__ __half g_w2v_h[(size_t)MAX_ROWS * DIM];

// ---- pass 1: fp32 -> fp16 table conversion ----------------------------------
// __ldcv: fetch-fresh, NO L2 allocation for the streamed fp32 reads. This
// keeps the 36 MB fp16 destination resident in L2 (writeback becomes lazy and
// overlaps the LTS-bound gather), and cuts convert's DRAM traffic to the pure
// 71 MB read.
__global__ __launch_bounds__(256)
void w2v_convert_kernel(const float4* __restrict__ src, uint2* __restrict__ dst, int n4)
{
    const int stride = gridDim.x * 256;
    int i = blockIdx.x * 256 + threadIdx.x;

    for (; i + 7 * stride < n4; i += 8 * stride) {
        float4 f[8];
        #pragma unroll
        for (int k = 0; k < 8; k++) f[k] = __ldcv(&src[i + k * stride]);
        #pragma unroll
        for (int k = 0; k < 8; k++) {
            __half2 a = __floats2half2_rn(f[k].x, f[k].y);
            __half2 b = __floats2half2_rn(f[k].z, f[k].w);
            uint2 u;
            u.x = *reinterpret_cast<unsigned*>(&a);
            u.y = *reinterpret_cast<unsigned*>(&b);
            dst[i + k * stride] = u;
        }
    }
    for (; i < n4; i += stride) {
        float4 f = __ldcv(&src[i]);
        __half2 a = __floats2half2_rn(f.x, f.y), b = __floats2half2_rn(f.z, f.w);
        uint2 u; u.x = *(unsigned*)&a; u.y = *(unsigned*)&b;
        dst[i] = u;
    }
}

// ---- pass 2: gather + pool (R9 structure — measured 19.6 us) -----------------
// Fine-grained: 32-thread CTAs, each CTA = (pool, row, dim-half).
//   CTAs [0, 2B)  : DESC  — cta/2 = row, cta&1 = half  (long work scheduled first)
//   CTAs [2B, 4B) : TITLE
// Thread owns 8 dims (one LDG.128 per token). Max via hmax2 (exact),
// sums via fp16 pair-add then fp32 accumulate. No cross-thread merging.
__global__ __launch_bounds__(32)
void swem_cat_kernel(const void* __restrict__ title_v,
                     const void* __restrict__ desc_v,
                     const void* __restrict__ tlen_v,
                     const void* __restrict__ dlen_v,
                     float* __restrict__ out,
                     int B)
{
    __shared__ int s_off[TD];     // pre-scaled byte offsets (idx * 1024)
    __shared__ int s_len;
    __shared__ int s_is64;

    const int cta = blockIdx.x;
    const int tid = threadIdx.x;
    const bool isDesc = (cta < 2 * B);
    const int local   = isDesc ? cta : (cta - 2 * B);
    const int b       = local >> 1;
    const int half    = local & 1;
    const int nTok    = isDesc ? TD : TT;

    // dtype detection: int64 vs int32 indices (values < 34836 => high word 0)
    {
        unsigned hi  = ((const unsigned*)title_v)[2 * tid + 1];
        unsigned any = __ballot_sync(0xffffffffu, hi != 0u);
        if (tid == 0) s_is64 = (any == 0u) ? 1 : 0;
    }
    __syncthreads();

    const void* idx_v = isDesc ? desc_v : title_v;
    const void* len_v = isDesc ? dlen_v : tlen_v;

    if (s_is64) {
        const long long* ip = (const long long*)idx_v + (long long)b * nTok;
        for (int i = tid; i < nTok; i += 32) s_off[i] = ((int)ip[i]) << 10;
        if (tid == 0) s_len = (int)((const long long*)len_v)[b];
    } else {
        const int* ip = (const int*)idx_v + b * nTok;
        for (int i = tid; i < nTok; i += 32) s_off[i] = ip[i] << 10;
        if (tid == 0) s_len = ((const int*)len_v)[b];
    }
    __syncthreads();

    const int len = s_len;
    // this CTA covers dims [half*256, half*256+256); thread slice = 8 dims
    const char* hbase = (const char*)g_w2v_h + half * 512 + tid * 16;
    float* orow = out + (size_t)b * (4 * DIM) + (isDesc ? DIM : 0)
                      + half * 256 + tid * 8;

    const __half2 NEGH2 = __halves2half2(__ushort_as_half(0xFC00),
                                         __ushort_as_half(0xFC00)); // (-inf,-inf)

    __half2 mx0 = NEGH2, mx1 = NEGH2, mx2 = NEGH2, mx3 = NEGH2;
    float sm0=0.f, sm1=0.f, sm2=0.f, sm3=0.f, sm4=0.f, sm5=0.f, sm6=0.f, sm7=0.f;

    int t = 0;
    #pragma unroll 4
    for (; t + 1 < len; t += 2) {
        const uint4 ua = *(const uint4*)(hbase + s_off[t]);
        const uint4 ub = *(const uint4*)(hbase + s_off[t + 1]);
        const __half2 a0 = *(const __half2*)&ua.x, a1 = *(const __half2*)&ua.y;
        const __half2 a2 = *(const __half2*)&ua.z, a3 = *(const __half2*)&ua.w;
        const __half2 b0 = *(const __half2*)&ub.x, b1 = *(const __half2*)&ub.y;
        const __half2 b2 = *(const __half2*)&ub.z, b3 = *(const __half2*)&ub.w;
        mx0 = __hmax2(mx0, __hmax2(a0, b0));
        mx1 = __hmax2(mx1, __hmax2(a1, b1));
        mx2 = __hmax2(mx2, __hmax2(a2, b2));
        mx3 = __hmax2(mx3, __hmax2(a3, b3));
        const __half2 p0 = __hadd2(a0, b0), p1 = __hadd2(a1, b1);
        const __half2 p2 = __hadd2(a2, b2), p3 = __hadd2(a3, b3);
        float2 f;
        f = __half22float2(p0); sm0 += f.x; sm1 += f.y;
        f = __half22float2(p1); sm2 += f.x; sm3 += f.y;
        f = __half22float2(p2); sm4 += f.x; sm5 += f.y;
        f = __half22float2(p3); sm6 += f.x; sm7 += f.y;
    }
    if (t < len) {   // odd tail token
        const uint4 u = *(const uint4*)(hbase + s_off[t]);
        const __half2 h0 = *(const __half2*)&u.x, h1 = *(const __half2*)&u.y;
        const __half2 h2 = *(const __half2*)&u.z, h3 = *(const __half2*)&u.w;
        mx0 = __hmax2(mx0, h0); mx1 = __hmax2(mx1, h1);
        mx2 = __hmax2(mx2, h2); mx3 = __hmax2(mx3, h3);
        float2 f;
        f = __half22float2(h0); sm0 += f.x; sm1 += f.y;
        f = __half22float2(h1); sm2 += f.x; sm3 += f.y;
        f = __half22float2(h2); sm4 += f.x; sm5 += f.y;
        f = __half22float2(h3); sm6 += f.x; sm7 += f.y;
    }

    float4 mxa, mxb, ava, avb;
    if (len > 0) {
        float2 m0 = __half22float2(mx0), m1 = __half22float2(mx1);
        float2 m2 = __half22float2(mx2), m3 = __half22float2(mx3);
        mxa = make_float4(m0.x, m0.y, m1.x, m1.y);
        mxb = make_float4(m2.x, m2.y, m3.x, m3.y);
        const float inv = 1.0f / (float)len;
        ava = make_float4(sm0 * inv, sm1 * inv, sm2 * inv, sm3 * inv);
        avb = make_float4(sm4 * inv, sm5 * inv, sm6 * inv, sm7 * inv);
    } else {
        mxa = mxb = ava = avb = make_float4(0.f, 0.f, 0.f, 0.f);
    }
    *(float4*)(orow)               = mxa;   // max quadrant
    *(float4*)(orow + 4)           = mxb;
    *(float4*)(orow + 2 * DIM)     = ava;   // avg quadrant (+2*DIM from max)
    *(float4*)(orow + 2 * DIM + 4) = avb;
}

extern "C" void kernel_launch(void* const* d_in, const int* in_sizes, int n_in,
                              void* d_out, int out_size)
{
    const void* title = d_in[0];
    const void* desc  = d_in[1];
    const void* tlen  = d_in[2];
    const void* dlen  = d_in[3];
    const float* w2v  = (const float*)d_in[n_in - 1];
    float* out        = (float*)d_out;

    const int B = in_sizes[2];                        // t_len has B elements

    long long w2v_elems = in_sizes[n_in - 1];
    long long rows = w2v_elems / DIM;
    if (rows > MAX_ROWS) rows = MAX_ROWS;
    const int n4 = (int)(rows * (DIM / 4));           // float4 chunks

    __half* dsth;
    cudaGetSymbolAddress((void**)&dsth, g_w2v_h);     // address only, no alloc

    w2v_convert_kernel<<<592, 256>>>((const float4*)w2v, (uint2*)dsth, n4);
    swem_cat_kernel<<<4 * B, 32>>>(title, desc, tlen, dlen, out, B);
}

// round 13
// speedup vs baseline: 2.6466x; 1.1232x over previous
#include <cuda_runtime.h>
#include <cuda_fp16.h>

#define TT  30
#define TD  150
#define DIM 512
#define MAX_ROWS 34836   // WORDS_CNT + 1

// fp16 copy of the embedding table (zero-init .bss, no allocation)
__device__ __half g_w2v_h[(size_t)MAX_ROWS * DIM];

// ---- pass 1: fp32 -> fp16 table conversion (measured-best: __ldcs, 592 CTAs)
__global__ __launch_bounds__(256)
void w2v_convert_kernel(const float4* __restrict__ src, uint2* __restrict__ dst, int n4)
{
    const int stride = gridDim.x * 256;
    int i = blockIdx.x * 256 + threadIdx.x;

    for (; i + 7 * stride < n4; i += 8 * stride) {
        float4 f[8];
        #pragma unroll
        for (int k = 0; k < 8; k++) f[k] = __ldcs(&src[i + k * stride]);
        #pragma unroll
        for (int k = 0; k < 8; k++) {
            __half2 a = __floats2half2_rn(f[k].x, f[k].y);
            __half2 b = __floats2half2_rn(f[k].z, f[k].w);
            uint2 u;
            u.x = *reinterpret_cast<unsigned*>(&a);
            u.y = *reinterpret_cast<unsigned*>(&b);
            dst[i + k * stride] = u;
        }
    }
    for (; i < n4; i += stride) {
        float4 f = __ldcs(&src[i]);
        __half2 a = __floats2half2_rn(f.x, f.y), b = __floats2half2_rn(f.z, f.w);
        uint2 u; u.x = *(unsigned*)&a; u.y = *(unsigned*)&b;
        dst[i] = u;
    }

    // Let the dependent gather kernel launch; its CTAs stage indices while we
    // finish streaming. Memory visibility is enforced by the consumer's
    // cudaGridDependencySynchronize().
    cudaTriggerProgrammaticLaunchCompletion();
}

// ---- pass 2: gather + pool (R9 structure — measured 19.4 us) -----------------
// Fine-grained: 32-thread CTAs, each CTA = (pool, row, dim-half).
//   CTAs [0, 2B)  : DESC (long work scheduled first);  CTAs [2B, 4B) : TITLE.
// Thread owns 8 dims (one LDG.128 per token). Max via hmax2 (exact),
// sums via fp16 pair-add then fp32 accumulate. No cross-thread merging.
// PDL: prologue (index staging) runs concurrently with the convert kernel;
// cudaGridDependencySynchronize() gates the first fp16-table access.
__global__ __launch_bounds__(32)
void swem_cat_kernel(const void* __restrict__ title_v,
                     const void* __restrict__ desc_v,
                     const void* __restrict__ tlen_v,
                     const void* __restrict__ dlen_v,
                     float* __restrict__ out,
                     int B)
{
    __shared__ int s_off[TD];     // pre-scaled byte offsets (idx * 1024)
    __shared__ int s_len;
    __shared__ int s_is64;

    const int cta = blockIdx.x;
    const int tid = threadIdx.x;
    const bool isDesc = (cta < 2 * B);
    const int local   = isDesc ? cta : (cta - 2 * B);
    const int b       = local >> 1;
    const int half    = local & 1;
    const int nTok    = isDesc ? TD : TT;

    // dtype detection: int64 vs int32 indices (values < 34836 => high word 0)
    {
        unsigned hi  = ((const unsigned*)title_v)[2 * tid + 1];
        unsigned any = __ballot_sync(0xffffffffu, hi != 0u);
        if (tid == 0) s_is64 = (any == 0u) ? 1 : 0;
    }
    __syncthreads();

    const void* idx_v = isDesc ? desc_v : title_v;
    const void* len_v = isDesc ? dlen_v : tlen_v;

    if (s_is64) {
        const long long* ip = (const long long*)idx_v + (long long)b * nTok;
        for (int i = tid; i < nTok; i += 32) s_off[i] = ((int)ip[i]) << 10;
        if (tid == 0) s_len = (int)((const long long*)len_v)[b];
    } else {
        const int* ip = (const int*)idx_v + b * nTok;
        for (int i = tid; i < nTok; i += 32) s_off[i] = ip[i] << 10;
        if (tid == 0) s_len = ((const int*)len_v)[b];
    }
    __syncthreads();

    // Wait until the convert kernel's fp16 table writes are visible.
    cudaGridDependencySynchronize();

    const int len = s_len;
    // this CTA covers dims [half*256, half*256+256); thread slice = 8 dims
    const char* hbase = (const char*)g_w2v_h + half * 512 + tid * 16;
    float* orow = out + (size_t)b * (4 * DIM) + (isDesc ? DIM : 0)
                      + half * 256 + tid * 8;

    const __half2 NEGH2 = __halves2half2(__ushort_as_half(0xFC00),
                                         __ushort_as_half(0xFC00)); // (-inf,-inf)

    __half2 mx0 = NEGH2, mx1 = NEGH2, mx2 = NEGH2, mx3 = NEGH2;
    float sm0=0.f, sm1=0.f, sm2=0.f, sm3=0.f, sm4=0.f, sm5=0.f, sm6=0.f, sm7=0.f;

    int t = 0;
    #pragma unroll 4
    for (; t + 1 < len; t += 2) {
        const uint4 ua = *(const uint4*)(hbase + s_off[t]);
        const uint4 ub = *(const uint4*)(hbase + s_off[t + 1]);
        const __half2 a0 = *(const __half2*)&ua.x, a1 = *(const __half2*)&ua.y;
        const __half2 a2 = *(const __half2*)&ua.z, a3 = *(const __half2*)&ua.w;
        const __half2 b0 = *(const __half2*)&ub.x, b1 = *(const __half2*)&ub.y;
        const __half2 b2 = *(const __half2*)&ub.z, b3 = *(const __half2*)&ub.w;
        mx0 = __hmax2(mx0, __hmax2(a0, b0));
        mx1 = __hmax2(mx1, __hmax2(a1, b1));
        mx2 = __hmax2(mx2, __hmax2(a2, b2));
        mx3 = __hmax2(mx3, __hmax2(a3, b3));
        const __half2 p0 = __hadd2(a0, b0), p1 = __hadd2(a1, b1);
        const __half2 p2 = __hadd2(a2, b2), p3 = __hadd2(a3, b3);
        float2 f;
        f = __half22float2(p0); sm0 += f.x; sm1 += f.y;
        f = __half22float2(p1); sm2 += f.x; sm3 += f.y;
        f = __half22float2(p2); sm4 += f.x; sm5 += f.y;
        f = __half22float2(p3); sm6 += f.x; sm7 += f.y;
    }
    if (t < len) {   // odd tail token
        const uint4 u = *(const uint4*)(hbase + s_off[t]);
        const __half2 h0 = *(const __half2*)&u.x, h1 = *(const __half2*)&u.y;
        const __half2 h2 = *(const __half2*)&u.z, h3 = *(const __half2*)&u.w;
        mx0 = __hmax2(mx0, h0); mx1 = __hmax2(mx1, h1);
        mx2 = __hmax2(mx2, h2); mx3 = __hmax2(mx3, h3);
        float2 f;
        f = __half22float2(h0); sm0 += f.x; sm1 += f.y;
        f = __half22float2(h1); sm2 += f.x; sm3 += f.y;
        f = __half22float2(h2); sm4 += f.x; sm5 += f.y;
        f = __half22float2(h3); sm6 += f.x; sm7 += f.y;
    }

    float4 mxa, mxb, ava, avb;
    if (len > 0) {
        float2 m0 = __half22float2(mx0), m1 = __half22float2(mx1);
        float2 m2 = __half22float2(mx2), m3 = __half22float2(mx3);
        mxa = make_float4(m0.x, m0.y, m1.x, m1.y);
        mxb = make_float4(m2.x, m2.y, m3.x, m3.y);
        const float inv = 1.0f / (float)len;
        ava = make_float4(sm0 * inv, sm1 * inv, sm2 * inv, sm3 * inv);
        avb = make_float4(sm4 * inv, sm5 * inv, sm6 * inv, sm7 * inv);
    } else {
        mxa = mxb = ava = avb = make_float4(0.f, 0.f, 0.f, 0.f);
    }
    *(float4*)(orow)               = mxa;   // max quadrant
    *(float4*)(orow + 4)           = mxb;
    *(float4*)(orow + 2 * DIM)     = ava;   // avg quadrant (+2*DIM from max)
    *(float4*)(orow + 2 * DIM + 4) = avb;
}

extern "C" void kernel_launch(void* const* d_in, const int* in_sizes, int n_in,
                              void* d_out, int out_size)
{
    const void* title = d_in[0];
    const void* desc  = d_in[1];
    const void* tlen  = d_in[2];
    const void* dlen  = d_in[3];
    const float* w2v  = (const float*)d_in[n_in - 1];
    float* out        = (float*)d_out;

    const int B = in_sizes[2];                        // t_len has B elements

    long long w2v_elems = in_sizes[n_in - 1];
    long long rows = w2v_elems / DIM;
    if (rows > MAX_ROWS) rows = MAX_ROWS;
    const int n4 = (int)(rows * (DIM / 4));           // float4 chunks

    __half* dsth;
    cudaGetSymbolAddress((void**)&dsth, g_w2v_h);     // address only, no alloc

    // primary: table conversion
    w2v_convert_kernel<<<592, 256>>>((const float4*)w2v, (uint2*)dsth, n4);

    // secondary: gather, launched with programmatic dependent launch so its
    // prologue overlaps the convert's DRAM-bound streaming phase.
    cudaLaunchConfig_t cfg = {};
    cfg.gridDim  = dim3(4 * B, 1, 1);
    cfg.blockDim = dim3(32, 1, 1);
    cudaLaunchAttribute attr[1];
    attr[0].id = cudaLaunchAttributeProgrammaticStreamSerialization;
    attr[0].val.programmaticStreamSerializationAllowed = 1;
    cfg.attrs = attr;
    cfg.numAttrs = 1;
    cudaLaunchKernelEx(&cfg, swem_cat_kernel, title, desc, tlen, dlen, out, B);
}

// round 14
// speedup vs baseline: 2.6644x; 1.0067x over previous
#include <cuda_runtime.h>
#include <cuda_fp16.h>

#define TT  30
#define TD  150
#define DIM 512
#define MAX_ROWS 34836   // WORDS_CNT + 1

// fp16 copy of the embedding table (zero-init .bss, no allocation)
__device__ __half g_w2v_h[(size_t)MAX_ROWS * DIM];

// ---- pass 1: fp32 -> fp16 table conversion (measured-best: __ldcs, 592 CTAs)
// Trigger at ENTRY: the dependent gather kernel may launch immediately and
// overlap its prologue with our DRAM-bound streaming. Its
// cudaGridDependencySynchronize() still waits for our full completion+flush,
// so correctness is unaffected.
__global__ __launch_bounds__(256)
void w2v_convert_kernel(const float4* __restrict__ src, uint2* __restrict__ dst, int n4)
{
    cudaTriggerProgrammaticLaunchCompletion();

    const int stride = gridDim.x * 256;
    int i = blockIdx.x * 256 + threadIdx.x;

    for (; i + 7 * stride < n4; i += 8 * stride) {
        float4 f[8];
        #pragma unroll
        for (int k = 0; k < 8; k++) f[k] = __ldcs(&src[i + k * stride]);
        #pragma unroll
        for (int k = 0; k < 8; k++) {
            __half2 a = __floats2half2_rn(f[k].x, f[k].y);
            __half2 b = __floats2half2_rn(f[k].z, f[k].w);
            uint2 u;
            u.x = *reinterpret_cast<unsigned*>(&a);
            u.y = *reinterpret_cast<unsigned*>(&b);
            dst[i + k * stride] = u;
        }
    }
    for (; i < n4; i += stride) {
        float4 f = __ldcs(&src[i]);
        __half2 a = __floats2half2_rn(f.x, f.y), b = __floats2half2_rn(f.z, f.w);
        uint2 u; u.x = *(unsigned*)&a; u.y = *(unsigned*)&b;
        dst[i] = u;
    }
}

// ---- pass 2: gather + pool (R9 structure — measured 19.4 us) -----------------
// Fine-grained: 32-thread CTAs, each CTA = (pool, row, dim-half).
//   CTAs [0, 2B)  : DESC (long work scheduled first);  CTAs [2B, 4B) : TITLE.
// Thread owns 8 dims (one LDG.128 per token). Max via hmax2 (exact),
// sums via fp16 pair-add then fp32 accumulate. No cross-thread merging.
// PDL: prologue (dtype detect + index staging) runs concurrently with the
// convert kernel; cudaGridDependencySynchronize() gates first table access.
__global__ __launch_bounds__(32)
void swem_cat_kernel(const void* __restrict__ title_v,
                     const void* __restrict__ desc_v,
                     const void* __restrict__ tlen_v,
                     const void* __restrict__ dlen_v,
                     float* __restrict__ out,
                     int B)
{
    __shared__ int s_off[TD];     // pre-scaled byte offsets (idx * 1024)
    __shared__ int s_len;
    __shared__ int s_is64;

    const int cta = blockIdx.x;
    const int tid = threadIdx.x;
    const bool isDesc = (cta < 2 * B);
    const int local   = isDesc ? cta : (cta - 2 * B);
    const int b       = local >> 1;
    const int half    = local & 1;
    const int nTok    = isDesc ? TD : TT;

    // dtype detection: int64 vs int32 indices (values < 34836 => high word 0)
    {
        unsigned hi  = ((const unsigned*)title_v)[2 * tid + 1];
        unsigned any = __ballot_sync(0xffffffffu, hi != 0u);
        if (tid == 0) s_is64 = (any == 0u) ? 1 : 0;
    }
    __syncthreads();

    const void* idx_v = isDesc ? desc_v : title_v;
    const void* len_v = isDesc ? dlen_v : tlen_v;

    if (s_is64) {
        const long long* ip = (const long long*)idx_v + (long long)b * nTok;
        for (int i = tid; i < nTok; i += 32) s_off[i] = ((int)ip[i]) << 10;
        if (tid == 0) s_len = (int)((const long long*)len_v)[b];
    } else {
        const int* ip = (const int*)idx_v + b * nTok;
        for (int i = tid; i < nTok; i += 32) s_off[i] = ip[i] << 10;
        if (tid == 0) s_len = ((const int*)len_v)[b];
    }
    __syncthreads();

    // Wait until the convert kernel's fp16 table writes are visible.
    cudaGridDependencySynchronize();

    const int len = s_len;
    // this CTA covers dims [half*256, half*256+256); thread slice = 8 dims
    const char* hbase = (const char*)g_w2v_h + half * 512 + tid * 16;
    float* orow = out + (size_t)b * (4 * DIM) + (isDesc ? DIM : 0)
                      + half * 256 + tid * 8;

    const __half2 NEGH2 = __halves2half2(__ushort_as_half(0xFC00),
                                         __ushort_as_half(0xFC00)); // (-inf,-inf)

    __half2 mx0 = NEGH2, mx1 = NEGH2, mx2 = NEGH2, mx3 = NEGH2;
    float sm0=0.f, sm1=0.f, sm2=0.f, sm3=0.f, sm4=0.f, sm5=0.f, sm6=0.f, sm7=0.f;

    int t = 0;
    #pragma unroll 4
    for (; t + 1 < len; t += 2) {
        const uint4 ua = *(const uint4*)(hbase + s_off[t]);
        const uint4 ub = *(const uint4*)(hbase + s_off[t + 1]);
        const __half2 a0 = *(const __half2*)&ua.x, a1 = *(const __half2*)&ua.y;
        const __half2 a2 = *(const __half2*)&ua.z, a3 = *(const __half2*)&ua.w;
        const __half2 b0 = *(const __half2*)&ub.x, b1 = *(const __half2*)&ub.y;
        const __half2 b2 = *(const __half2*)&ub.z, b3 = *(const __half2*)&ub.w;
        mx0 = __hmax2(mx0, __hmax2(a0, b0));
        mx1 = __hmax2(mx1, __hmax2(a1, b1));
        mx2 = __hmax2(mx2, __hmax2(a2, b2));
        mx3 = __hmax2(mx3, __hmax2(a3, b3));
        const __half2 p0 = __hadd2(a0, b0), p1 = __hadd2(a1, b1);
        const __half2 p2 = __hadd2(a2, b2), p3 = __hadd2(a3, b3);
        float2 f;
        f = __half22float2(p0); sm0 += f.x; sm1 += f.y;
        f = __half22float2(p1); sm2 += f.x; sm3 += f.y;
        f = __half22float2(p2); sm4 += f.x; sm5 += f.y;
        f = __half22float2(p3); sm6 += f.x; sm7 += f.y;
    }
    if (t < len) {   // odd tail token
        const uint4 u = *(const uint4*)(hbase + s_off[t]);
        const __half2 h0 = *(const __half2*)&u.x, h1 = *(const __half2*)&u.y;
        const __half2 h2 = *(const __half2*)&u.z, h3 = *(const __half2*)&u.w;
        mx0 = __hmax2(mx0, h0); mx1 = __hmax2(mx1, h1);
        mx2 = __hmax2(mx2, h2); mx3 = __hmax2(mx3, h3);
        float2 f;
        f = __half22float2(h0); sm0 += f.x; sm1 += f.y;
        f = __half22float2(h1); sm2 += f.x; sm3 += f.y;
        f = __half22float2(h2); sm4 += f.x; sm5 += f.y;
        f = __half22float2(h3); sm6 += f.x; sm7 += f.y;
    }

    float4 mxa, mxb, ava, avb;
    if (len > 0) {
        float2 m0 = __half22float2(mx0), m1 = __half22float2(mx1);
        float2 m2 = __half22float2(mx2), m3 = __half22float2(mx3);
        mxa = make_float4(m0.x, m0.y, m1.x, m1.y);
        mxb = make_float4(m2.x, m2.y, m3.x, m3.y);
        const float inv = 1.0f / (float)len;
        ava = make_float4(sm0 * inv, sm1 * inv, sm2 * inv, sm3 * inv);
        avb = make_float4(sm4 * inv, sm5 * inv, sm6 * inv, sm7 * inv);
    } else {
        mxa = mxb = ava = avb = make_float4(0.f, 0.f, 0.f, 0.f);
    }
    *(float4*)(orow)               = mxa;   // max quadrant
    *(float4*)(orow + 4)           = mxb;
    *(float4*)(orow + 2 * DIM)     = ava;   // avg quadrant (+2*DIM from max)
    *(float4*)(orow + 2 * DIM + 4) = avb;
}

extern "C" void kernel_launch(void* const* d_in, const int* in_sizes, int n_in,
                              void* d_out, int out_size)
{
    const void* title = d_in[0];
    const void* desc  = d_in[1];
    const void* tlen  = d_in[2];
    const void* dlen  = d_in[3];
    const float* w2v  = (const float*)d_in[n_in - 1];
    float* out        = (float*)d_out;

    const int B = in_sizes[2];                        // t_len has B elements

    long long w2v_elems = in_sizes[n_in - 1];
    long long rows = w2v_elems / DIM;
    if (rows > MAX_ROWS) rows = MAX_ROWS;
    const int n4 = (int)(rows * (DIM / 4));           // float4 chunks

    __half* dsth;
    cudaGetSymbolAddress((void**)&dsth, g_w2v_h);     // address only, no alloc

    // primary: table conversion (triggers PDL at entry)
    w2v_convert_kernel<<<592, 256>>>((const float4*)w2v, (uint2*)dsth, n4);

    // secondary: gather, launched with programmatic dependent launch so its
    // prologue overlaps the convert's DRAM-bound streaming phase.
    cudaLaunchConfig_t cfg = {};
    cfg.gridDim  = dim3(4 * B, 1, 1);
    cfg.blockDim = dim3(32, 1, 1);
    cudaLaunchAttribute attr[1];
    attr[0].id = cudaLaunchAttributeProgrammaticStreamSerialization;
    attr[0].val.programmaticStreamSerializationAllowed = 1;
    cfg.attrs = attr;
    cfg.numAttrs = 1;
    cudaLaunchKernelEx(&cfg, swem_cat_kernel, title, desc, tlen, dlen, out, B);
}